// round 2
// baseline (speedup 1.0000x reference)
#include <cuda_runtime.h>
#include <math.h>

// Problem constants (fixed by the reference)
#define BATCH 8192
#define NCLS  1000
#define DDIM  4096

// Fused segment-sum kernel tiling
#define TILE_D        512          // columns per block (float4 x 128 threads)
#define FUSED_THREADS 128
#define NT_D          (DDIM / TILE_D)   // 8 tiles over D

// ---------------------------------------------------------------------------
// Device scratch (no allocations allowed)
// ---------------------------------------------------------------------------
__device__ int   g_counts[NCLS];
__device__ int   g_cursor[NCLS];
__device__ int   g_offsets[NCLS + 1];
__device__ int   g_rows[BATCH];
__device__ float g_l1_part[BATCH];          // per-row CE contribution (lse - logit_t)
__device__ float g_l2_part[NT_D * NCLS];    // per-block BCE partial sums

// ---------------------------------------------------------------------------
// 1) zero counters
// ---------------------------------------------------------------------------
__global__ void zero_kernel() {
    int i = blockIdx.x * blockDim.x + threadIdx.x;
    if (i < NCLS) { g_counts[i] = 0; g_cursor[i] = 0; }
}

// ---------------------------------------------------------------------------
// 2) histogram of target
// ---------------------------------------------------------------------------
__global__ void hist_kernel(const int* __restrict__ target) {
    int i = blockIdx.x * blockDim.x + threadIdx.x;
    if (i < BATCH) atomicAdd(&g_counts[target[i]], 1);
}

// ---------------------------------------------------------------------------
// 3) single-block scan over 1000 counts -> offsets; also emit total_accumulated
// ---------------------------------------------------------------------------
__global__ void scan_kernel(float* __restrict__ total_out) {
    __shared__ int s[1024];
    int tid = threadIdx.x;
    int v = (tid < NCLS) ? g_counts[tid] : 0;
    s[tid] = v;
    __syncthreads();
    #pragma unroll
    for (int off = 1; off < 1024; off <<= 1) {
        int t = (tid >= off) ? s[tid - off] : 0;
        __syncthreads();
        s[tid] += t;
        __syncthreads();
    }
    if (tid < NCLS) {
        g_offsets[tid + 1] = s[tid];
        if (tid == 0) g_offsets[0] = 0;
        total_out[tid] = (float)v;
    }
}

// ---------------------------------------------------------------------------
// 4) scatter row ids into class-sorted order (CSR)
// ---------------------------------------------------------------------------
__global__ void scatter_kernel(const int* __restrict__ target) {
    int i = blockIdx.x * blockDim.x + threadIdx.x;
    if (i < BATCH) {
        int t = target[i];
        int p = atomicAdd(&g_cursor[t], 1);
        g_rows[g_offsets[t] + p] = i;
    }
}

// ---------------------------------------------------------------------------
// 5) fused: per-(class, D-tile) block sums sigmoid(dense_out) over its rows
//    and accumulates the BCE loss against dense_labels[class] (read once).
//    NOTE: out_sum is only 4B-aligned (sits at d_out+1 float), so the result
//    tile is written with scalar stores; input streams stay float4.
// ---------------------------------------------------------------------------
__global__ __launch_bounds__(FUSED_THREADS)
void fused_kernel(const float* __restrict__ dense_out,
                  const float* __restrict__ dense_labels,
                  float* __restrict__ out_sum) {
    const int c   = blockIdx.y;
    const int col = blockIdx.x * TILE_D + threadIdx.x * 4;

    const float4 y4 = *reinterpret_cast<const float4*>(
        dense_labels + (size_t)c * DDIM + col);

    float4 acc = make_float4(0.f, 0.f, 0.f, 0.f);
    float bce = 0.f;

    const int s = g_offsets[c];
    const int e = g_offsets[c + 1];
    for (int i = s; i < e; i++) {
        const int r = g_rows[i];
        const float4 x4 = *reinterpret_cast<const float4*>(
            dense_out + (size_t)r * DDIM + col);

        // sigmoid for the segment sum
        acc.x += 1.f / (1.f + __expf(-x4.x));
        acc.y += 1.f / (1.f + __expf(-x4.y));
        acc.z += 1.f / (1.f + __expf(-x4.z));
        acc.w += 1.f / (1.f + __expf(-x4.w));

        // stable BCEWithLogits term: max(x,0) - x*y + log1p(exp(-|x|))
        bce += fmaxf(x4.x, 0.f) - x4.x * y4.x + log1pf(__expf(-fabsf(x4.x)));
        bce += fmaxf(x4.y, 0.f) - x4.y * y4.y + log1pf(__expf(-fabsf(x4.y)));
        bce += fmaxf(x4.z, 0.f) - x4.z * y4.z + log1pf(__expf(-fabsf(x4.z)));
        bce += fmaxf(x4.w, 0.f) - x4.w * y4.w + log1pf(__expf(-fabsf(x4.w)));
    }

    // scalar stores: destination is only 4B-aligned (d_out + 1 float)
    float* dst = out_sum + (size_t)c * DDIM + col;
    dst[0] = acc.x;
    dst[1] = acc.y;
    dst[2] = acc.z;
    dst[3] = acc.w;

    // block-reduce bce
    #pragma unroll
    for (int o = 16; o; o >>= 1) bce += __shfl_xor_sync(0xffffffffu, bce, o);
    __shared__ float sw[FUSED_THREADS / 32];
    if ((threadIdx.x & 31) == 0) sw[threadIdx.x >> 5] = bce;
    __syncthreads();
    if (threadIdx.x == 0) {
        float t = 0.f;
        #pragma unroll
        for (int w = 0; w < FUSED_THREADS / 32; w++) t += sw[w];
        g_l2_part[c * NT_D + blockIdx.x] = t;
    }
}

// ---------------------------------------------------------------------------
// 6) cross-entropy: one block per batch row; two-pass logsumexp in registers
// ---------------------------------------------------------------------------
#define CE_THREADS 128
__global__ __launch_bounds__(CE_THREADS)
void ce_kernel(const float* __restrict__ logits, const int* __restrict__ target) {
    const int row = blockIdx.x;
    const float* lrow = logits + (size_t)row * NCLS;
    const int tid = threadIdx.x;

    float vals[8];
    float mx = -INFINITY;
    #pragma unroll
    for (int k = 0; k < 8; k++) {
        int j = tid + k * CE_THREADS;
        vals[k] = (j < NCLS) ? lrow[j] : -INFINITY;
        mx = fmaxf(mx, vals[k]);
    }

    __shared__ float sred[CE_THREADS / 32];
    // block max
    #pragma unroll
    for (int o = 16; o; o >>= 1) mx = fmaxf(mx, __shfl_xor_sync(0xffffffffu, mx, o));
    if ((tid & 31) == 0) sred[tid >> 5] = mx;
    __syncthreads();
    float bm = sred[0];
    #pragma unroll
    for (int w = 1; w < CE_THREADS / 32; w++) bm = fmaxf(bm, sred[w]);
    __syncthreads();

    float sum = 0.f;
    #pragma unroll
    for (int k = 0; k < 8; k++) {
        int j = tid + k * CE_THREADS;
        if (j < NCLS) sum += __expf(vals[k] - bm);
    }
    #pragma unroll
    for (int o = 16; o; o >>= 1) sum += __shfl_xor_sync(0xffffffffu, sum, o);
    if ((tid & 31) == 0) sred[tid >> 5] = sum;
    __syncthreads();
    if (tid == 0) {
        float bs = 0.f;
        #pragma unroll
        for (int w = 0; w < CE_THREADS / 32; w++) bs += sred[w];
        float lse = bm + __logf(bs);
        float lt  = lrow[target[row]];
        g_l1_part[row] = lse - lt;
    }
}

// ---------------------------------------------------------------------------
// 7) finalize: reduce partials in double, write loss scalar
// ---------------------------------------------------------------------------
#define FIN_THREADS 256
__global__ __launch_bounds__(FIN_THREADS)
void finalize_kernel(float* __restrict__ out_loss) {
    const int tid = threadIdx.x;
    double s1 = 0.0, s2 = 0.0;
    for (int i = tid; i < BATCH; i += FIN_THREADS) s1 += (double)g_l1_part[i];
    for (int i = tid; i < NT_D * NCLS; i += FIN_THREADS) s2 += (double)g_l2_part[i];

    __shared__ double sh1[FIN_THREADS];
    __shared__ double sh2[FIN_THREADS];
    sh1[tid] = s1; sh2[tid] = s2;
    __syncthreads();
    for (int o = FIN_THREADS / 2; o > 0; o >>= 1) {
        if (tid < o) { sh1[tid] += sh1[tid + o]; sh2[tid] += sh2[tid + o]; }
        __syncthreads();
    }
    if (tid == 0) {
        double loss1 = sh1[0] / (double)BATCH;
        double loss2 = sh2[0] / ((double)BATCH * (double)DDIM);
        out_loss[0] = (float)(0.5 * loss1 + 0.5 * loss2);
    }
}

// ---------------------------------------------------------------------------
// Launch. Output layout (float32): [loss(1) | dense_output_sum(C*D) | total(C)]
// ---------------------------------------------------------------------------
extern "C" void kernel_launch(void* const* d_in, const int* in_sizes, int n_in,
                              void* d_out, int out_size) {
    const float* logits       = (const float*)d_in[0]; // [B, C]
    const float* dense_out    = (const float*)d_in[1]; // [B, D]
    const int*   target       = (const int*)  d_in[2]; // [B]
    const float* dense_labels = (const float*)d_in[3]; // [C, D]

    float* out       = (float*)d_out;
    float* out_loss  = out;
    float* out_sum   = out + 1;
    float* out_total = out + 1 + (size_t)NCLS * DDIM;

    zero_kernel<<<(NCLS + 255) / 256, 256>>>();
    hist_kernel<<<(BATCH + 255) / 256, 256>>>(target);
    scan_kernel<<<1, 1024>>>(out_total);
    scatter_kernel<<<(BATCH + 255) / 256, 256>>>(target);

    dim3 fgrid(NT_D, NCLS);
    fused_kernel<<<fgrid, FUSED_THREADS>>>(dense_out, dense_labels, out_sum);

    ce_kernel<<<BATCH, CE_THREADS>>>(logits, target);

    finalize_kernel<<<1, FIN_THREADS>>>(out_loss);
}

// round 3
// speedup vs baseline: 1.0480x; 1.0480x over previous
#include <cuda_runtime.h>
#include <math.h>

// Problem constants (fixed by the reference)
#define BATCH 8192
#define NCLS  1000
#define DDIM  4096

// Fused segment-sum kernel tiling: 128 threads x 2 float4 = 1024 floats/block
#define TILE_D        1024
#define FUSED_THREADS 128
#define NT_D          (DDIM / TILE_D)   // 4 tiles over D
#define ROW_CHUNK     128               // row indices staged in smem per chunk

// ---------------------------------------------------------------------------
// Device scratch (no allocations allowed)
// ---------------------------------------------------------------------------
__device__ int   g_offsets[NCLS + 1];
__device__ int   g_rows[BATCH];
__device__ float g_l1_part[BATCH];          // per-row CE contribution (lse - logit_t)
__device__ float g_l2_part[NT_D * NCLS];    // per-block BCE partial sums

// ---------------------------------------------------------------------------
// 1) prep: histogram + scan + scatter + total_accumulated, one block
// ---------------------------------------------------------------------------
__global__ __launch_bounds__(1024)
void prep_kernel(const int* __restrict__ target, float* __restrict__ total_out) {
    __shared__ int scnt[1024];   // counts -> later cursors
    __shared__ int sscan[1024];  // inclusive scan workspace
    const int tid = threadIdx.x;

    scnt[tid] = 0;
    __syncthreads();

    // histogram via shared atomics
    #pragma unroll
    for (int i = tid; i < BATCH; i += 1024)
        atomicAdd(&scnt[target[i]], 1);
    __syncthreads();

    const int v = scnt[tid];
    if (tid < NCLS) total_out[tid] = (float)v;

    // Hillis-Steele inclusive scan
    sscan[tid] = v;
    __syncthreads();
    #pragma unroll
    for (int off = 1; off < 1024; off <<= 1) {
        int t = (tid >= off) ? sscan[tid - off] : 0;
        __syncthreads();
        sscan[tid] += t;
        __syncthreads();
    }

    const int incl = sscan[tid];
    if (tid < NCLS) {
        g_offsets[tid + 1] = incl;
        if (tid == 0) g_offsets[0] = 0;
    }

    // cursors = exclusive offsets; scatter row ids
    scnt[tid] = incl - v;
    __syncthreads();
    #pragma unroll
    for (int i = tid; i < BATCH; i += 1024) {
        int t = target[i];
        int p = atomicAdd(&scnt[t], 1);
        g_rows[p] = i;
    }
}

// ---------------------------------------------------------------------------
// 2) fused: per-(class, D-tile) block sums sigmoid(dense_out) over its rows
//    and accumulates BCE vs dense_labels[class] (label tile read once).
//    Row indices staged in smem; row loop pipelined x2 -> 4 outstanding LDG.
//    NOTE: out_sum is only 4B-aligned (d_out + 1 float) -> scalar stores.
// ---------------------------------------------------------------------------
__device__ __forceinline__ void acc_one(const float4 x4, const float4 y4,
                                        float4& acc, float& bce) {
    acc.x += 1.f / (1.f + __expf(-x4.x));
    acc.y += 1.f / (1.f + __expf(-x4.y));
    acc.z += 1.f / (1.f + __expf(-x4.z));
    acc.w += 1.f / (1.f + __expf(-x4.w));
    bce += fmaxf(x4.x, 0.f) - x4.x * y4.x + log1pf(__expf(-fabsf(x4.x)));
    bce += fmaxf(x4.y, 0.f) - x4.y * y4.y + log1pf(__expf(-fabsf(x4.y)));
    bce += fmaxf(x4.z, 0.f) - x4.z * y4.z + log1pf(__expf(-fabsf(x4.z)));
    bce += fmaxf(x4.w, 0.f) - x4.w * y4.w + log1pf(__expf(-fabsf(x4.w)));
}

__global__ __launch_bounds__(FUSED_THREADS)
void fused_kernel(const float* __restrict__ dense_out,
                  const float* __restrict__ dense_labels,
                  float* __restrict__ out_sum) {
    __shared__ int srows[ROW_CHUNK];
    const int c    = blockIdx.y;
    const int col0 = blockIdx.x * TILE_D + threadIdx.x * 4;
    const int col1 = col0 + (TILE_D / 2);

    const float4 y0 = *reinterpret_cast<const float4*>(
        dense_labels + (size_t)c * DDIM + col0);
    const float4 y1 = *reinterpret_cast<const float4*>(
        dense_labels + (size_t)c * DDIM + col1);

    float4 acc0 = make_float4(0.f, 0.f, 0.f, 0.f);
    float4 acc1 = make_float4(0.f, 0.f, 0.f, 0.f);
    float bce = 0.f;

    const int s = g_offsets[c];
    const int e = g_offsets[c + 1];

    for (int base = s; base < e; base += ROW_CHUNK) {
        const int n = min(ROW_CHUNK, e - base);
        if (threadIdx.x < n) srows[threadIdx.x] = g_rows[base + threadIdx.x];
        __syncthreads();

        int j = 0;
        // pipelined x2: 4 independent float4 loads in flight per thread
        for (; j + 1 < n; j += 2) {
            const size_t r0 = (size_t)srows[j]     * DDIM;
            const size_t r1 = (size_t)srows[j + 1] * DDIM;
            const float4 a0 = *reinterpret_cast<const float4*>(dense_out + r0 + col0);
            const float4 a1 = *reinterpret_cast<const float4*>(dense_out + r0 + col1);
            const float4 b0 = *reinterpret_cast<const float4*>(dense_out + r1 + col0);
            const float4 b1 = *reinterpret_cast<const float4*>(dense_out + r1 + col1);
            acc_one(a0, y0, acc0, bce);
            acc_one(a1, y1, acc1, bce);
            acc_one(b0, y0, acc0, bce);
            acc_one(b1, y1, acc1, bce);
        }
        if (j < n) {
            const size_t r0 = (size_t)srows[j] * DDIM;
            const float4 a0 = *reinterpret_cast<const float4*>(dense_out + r0 + col0);
            const float4 a1 = *reinterpret_cast<const float4*>(dense_out + r0 + col1);
            acc_one(a0, y0, acc0, bce);
            acc_one(a1, y1, acc1, bce);
        }
        __syncthreads();
    }

    // scalar stores: destination only 4B-aligned
    float* dst0 = out_sum + (size_t)c * DDIM + col0;
    dst0[0] = acc0.x; dst0[1] = acc0.y; dst0[2] = acc0.z; dst0[3] = acc0.w;
    float* dst1 = out_sum + (size_t)c * DDIM + col1;
    dst1[0] = acc1.x; dst1[1] = acc1.y; dst1[2] = acc1.z; dst1[3] = acc1.w;

    // block-reduce bce
    #pragma unroll
    for (int o = 16; o; o >>= 1) bce += __shfl_xor_sync(0xffffffffu, bce, o);
    __shared__ float sw[FUSED_THREADS / 32];
    if ((threadIdx.x & 31) == 0) sw[threadIdx.x >> 5] = bce;
    __syncthreads();
    if (threadIdx.x == 0) {
        float t = 0.f;
        #pragma unroll
        for (int w = 0; w < FUSED_THREADS / 32; w++) t += sw[w];
        g_l2_part[c * NT_D + blockIdx.x] = t;
    }
}

// ---------------------------------------------------------------------------
// 3) cross-entropy: one block per batch row; float4, two-pass logsumexp
//    1000 floats = 250 float4; row stride 4000B is 16B-aligned.
// ---------------------------------------------------------------------------
#define CE_THREADS 128
__global__ __launch_bounds__(CE_THREADS)
void ce_kernel(const float* __restrict__ logits, const int* __restrict__ target) {
    const int row = blockIdx.x;
    const float4* lrow4 = reinterpret_cast<const float4*>(logits + (size_t)row * NCLS);
    const int tid = threadIdx.x;

    float4 v0 = make_float4(-INFINITY, -INFINITY, -INFINITY, -INFINITY);
    float4 v1 = v0;
    v0 = lrow4[tid];                              // tid in [0,128) < 250
    const bool has1 = (tid + CE_THREADS) < 250;   // 250 float4 total
    if (has1) v1 = lrow4[tid + CE_THREADS];

    float mx = fmaxf(fmaxf(v0.x, v0.y), fmaxf(v0.z, v0.w));
    mx = fmaxf(mx, fmaxf(fmaxf(v1.x, v1.y), fmaxf(v1.z, v1.w)));

    __shared__ float sred[CE_THREADS / 32];
    #pragma unroll
    for (int o = 16; o; o >>= 1) mx = fmaxf(mx, __shfl_xor_sync(0xffffffffu, mx, o));
    if ((tid & 31) == 0) sred[tid >> 5] = mx;
    __syncthreads();
    float bm = fmaxf(fmaxf(sred[0], sred[1]), fmaxf(sred[2], sred[3]));
    __syncthreads();

    float sum = __expf(v0.x - bm) + __expf(v0.y - bm) +
                __expf(v0.z - bm) + __expf(v0.w - bm);
    if (has1)
        sum += __expf(v1.x - bm) + __expf(v1.y - bm) +
               __expf(v1.z - bm) + __expf(v1.w - bm);

    #pragma unroll
    for (int o = 16; o; o >>= 1) sum += __shfl_xor_sync(0xffffffffu, sum, o);
    if ((tid & 31) == 0) sred[tid >> 5] = sum;
    __syncthreads();
    if (tid == 0) {
        float bs = sred[0] + sred[1] + sred[2] + sred[3];
        float lse = bm + __logf(bs);
        float lt  = logits[(size_t)row * NCLS + target[row]];
        g_l1_part[row] = lse - lt;
    }
}

// ---------------------------------------------------------------------------
// 4) finalize: reduce partials in double, write loss scalar
// ---------------------------------------------------------------------------
#define FIN_THREADS 256
__global__ __launch_bounds__(FIN_THREADS)
void finalize_kernel(float* __restrict__ out_loss) {
    const int tid = threadIdx.x;
    double s1 = 0.0, s2 = 0.0;
    for (int i = tid; i < BATCH; i += FIN_THREADS) s1 += (double)g_l1_part[i];
    for (int i = tid; i < NT_D * NCLS; i += FIN_THREADS) s2 += (double)g_l2_part[i];

    __shared__ double sh1[FIN_THREADS];
    __shared__ double sh2[FIN_THREADS];
    sh1[tid] = s1; sh2[tid] = s2;
    __syncthreads();
    for (int o = FIN_THREADS / 2; o > 0; o >>= 1) {
        if (tid < o) { sh1[tid] += sh1[tid + o]; sh2[tid] += sh2[tid + o]; }
        __syncthreads();
    }
    if (tid == 0) {
        double loss1 = sh1[0] / (double)BATCH;
        double loss2 = sh2[0] / ((double)BATCH * (double)DDIM);
        out_loss[0] = (float)(0.5 * loss1 + 0.5 * loss2);
    }
}

// ---------------------------------------------------------------------------
// Launch. Output layout (float32): [loss(1) | dense_output_sum(C*D) | total(C)]
// ---------------------------------------------------------------------------
extern "C" void kernel_launch(void* const* d_in, const int* in_sizes, int n_in,
                              void* d_out, int out_size) {
    const float* logits       = (const float*)d_in[0]; // [B, C]
    const float* dense_out    = (const float*)d_in[1]; // [B, D]
    const int*   target       = (const int*)  d_in[2]; // [B]
    const float* dense_labels = (const float*)d_in[3]; // [C, D]

    float* out       = (float*)d_out;
    float* out_loss  = out;
    float* out_sum   = out + 1;
    float* out_total = out + 1 + (size_t)NCLS * DDIM;

    prep_kernel<<<1, 1024>>>(target, out_total);

    dim3 fgrid(NT_D, NCLS);
    fused_kernel<<<fgrid, FUSED_THREADS>>>(dense_out, dense_labels, out_sum);

    ce_kernel<<<BATCH, CE_THREADS>>>(logits, target);

    finalize_kernel<<<1, FIN_THREADS>>>(out_loss);
}